// round 8
// baseline (speedup 1.0000x reference)
#include <cuda_runtime.h>
#include <cuda_bf16.h>
#include <cstdint>
#include <math.h>

typedef unsigned int u32;

#define BB 2
#define NN 8192
#define CC 128
#define KNB 16
#define EPSF 1e-5f

// bf16 plane row stride: 136 elems = 272 bytes (ldmatrix conflict-free padding)
#define BSTR 272
#define PLANE 34816     // 128-row plane bytes (qkv kernel)
#define APLANE 17408    // 64-row plane bytes (main kernel A tiles)

// ---- main kernel smem offsets (bytes), total ~106KB -> 2 blocks/SM
#define OFF_AHI 0
#define OFF_ALO 17408
#define OFF_W   34816
#define OFF_VP  69632
#define OFF_Q   103424
#define OFF_OUT 105472
#define OFF_NX  107520
#define OFF_NY  107776
#define OFF_NZ  108032
#define OFF_QXYZ 108288
#define OFF_IDX  108336
#define MAIN_SMEM 108608

#define QKV_SMEM 139264
#define KNN_SMEM 57344

// ---------------- device scratch ----------------
__device__ float g_q[BB*NN*CC];
__device__ float g_k[BB*NN*CC];
__device__ float g_v[BB*NN*CC];
__device__ int   g_idx[BB*NN*KNB];
__device__ float g_pW1f[CC*3];
__device__ float g_pb1f[CC];
__device__ float g_ab1f[CC];
// pre-split weight planes for main kernel: [pW2, aW1f, aW2] x [hi, lo], padded BSTR layout
__device__ __align__(16) u32 g_wpl[3][2][8704];

// ---------------- helpers ----------------
__device__ __forceinline__ u32 cvta_s(const void* p) {
    return (u32)__cvta_generic_to_shared(p);
}
__device__ __forceinline__ u32 packbf(float x, float y) {
    u32 r; asm("cvt.rn.bf16x2.f32 %0, %1, %2;" : "=r"(r) : "f"(y), "f"(x)); return r;
}
__device__ __forceinline__ float bhi(float v) {
    return __bfloat162float(__float2bfloat16(v));
}
__device__ __forceinline__ void split_lin(char* hiP, char* loP, int off, float x, float y) {
    float hx = bhi(x), hy = bhi(y);
    *(u32*)(hiP + off) = packbf(hx, hy);
    *(u32*)(loP + off) = packbf(x - hx, y - hy);
}
__device__ __forceinline__ void ldsm4(u32 addr, u32 r[4]) {
    asm volatile("ldmatrix.sync.aligned.m8n8.x4.shared.b16 {%0,%1,%2,%3},[%4];"
                 : "=r"(r[0]), "=r"(r[1]), "=r"(r[2]), "=r"(r[3]) : "r"(addr));
}
__device__ __forceinline__ void mma_bf16(float c[4], const u32 a[4], u32 b0, u32 b1) {
    asm volatile("mma.sync.aligned.m16n8k16.row.col.f32.bf16.bf16.f32 "
                 "{%0,%1,%2,%3},{%4,%5,%6,%7},{%8,%9},{%0,%1,%2,%3};"
                 : "+f"(c[0]), "+f"(c[1]), "+f"(c[2]), "+f"(c[3])
                 : "r"(a[0]), "r"(a[1]), "r"(a[2]), "r"(a[3]), "r"(b0), "r"(b1));
}
// reductions over the 16 rows of one query (lanes xor 4,8,16; both acc rows per lane)
__device__ __forceinline__ float redmax(float v) {
    v = fmaxf(v, __shfl_xor_sync(0xffffffffu, v, 4));
    v = fmaxf(v, __shfl_xor_sync(0xffffffffu, v, 8));
    v = fmaxf(v, __shfl_xor_sync(0xffffffffu, v, 16));
    return v;
}
__device__ __forceinline__ float redsum(float v) {
    v += __shfl_xor_sync(0xffffffffu, v, 4);
    v += __shfl_xor_sync(0xffffffffu, v, 8);
    v += __shfl_xor_sync(0xffffffffu, v, 16);
    return v;
}

// ---------------- fold BN + pre-split main weights ----------------
__global__ void fold_kernel(const float* __restrict__ pW1, const float* __restrict__ pb1,
                            const float* __restrict__ pg,  const float* __restrict__ pbeta,
                            const float* __restrict__ pmean,const float* __restrict__ pvar,
                            const float* __restrict__ aW1, const float* __restrict__ ab1,
                            const float* __restrict__ ag,  const float* __restrict__ abeta,
                            const float* __restrict__ amean,const float* __restrict__ avar,
                            const float* __restrict__ pW2, const float* __restrict__ aW2)
{
    int tid = threadIdx.x;      // 512 threads
    if (tid < CC) {
        int o = tid;
        float s = pg[o] * rsqrtf(pvar[o] + EPSF);
        g_pW1f[o*3+0] = pW1[o*3+0] * s;
        g_pW1f[o*3+1] = pW1[o*3+1] * s;
        g_pW1f[o*3+2] = pW1[o*3+2] * s;
        g_pb1f[o] = pb1[o]*s + pbeta[o] - pmean[o]*s;
        float sa = ag[o] * rsqrtf(avar[o] + EPSF);
        g_ab1f[o] = ab1[o]*sa + abeta[o] - amean[o]*sa;
    }
    // split pW2 / aW1f / aW2 into hi/lo bf16 planes (BSTR-padded layout)
    for (int e = tid; e < 3*8192; e += 512) {
        int widx = e >> 13, idx = e & 8191;
        int o = idx >> 6, kp = idx & 63;
        float w0, w1;
        if (widx == 0)      { w0 = pW2[o*128 + 2*kp]; w1 = pW2[o*128 + 2*kp + 1]; }
        else if (widx == 1) {
            float sa = ag[o] * rsqrtf(avar[o] + EPSF);
            w0 = aW1[o*128 + 2*kp] * sa; w1 = aW1[o*128 + 2*kp + 1] * sa;
        } else              { w0 = aW2[o*128 + 2*kp]; w1 = aW2[o*128 + 2*kp + 1]; }
        float h0 = bhi(w0), h1 = bhi(w1);
        g_wpl[widx][0][o*68 + kp] = packbf(h0, h1);
        g_wpl[widx][1][o*68 + kp] = packbf(w0 - h0, w1 - h1);
    }
}

// ---------------- KNN: 4 threads per query ----------------
__global__ __launch_bounds__(256, 1) void knn_kernel(const float* __restrict__ xyz)
{
    extern __shared__ float ksm[];
    float* sx = ksm;
    float* sy = sx + 2048;
    float* sz = sy + 2048;
    float* ss = sz + 2048;
    float* sMD = ss + 2048;
    int*   sMI = (int*)(sMD + 3072);

    const int tid = threadIdx.x;
    const int qloc = tid >> 2;
    const int par  = tid & 3;
    const int b = blockIdx.x >> 7;
    const int n = ((blockIdx.x & 127) << 6) + qloc;
    const float* base = xyz + (size_t)b * NN * 3;

    float qx = base[n*3+0], qy = base[n*3+1], qz = base[n*3+2];
    float qs = qx*qx + qy*qy + qz*qz;

    float bd[KNB]; int bi[KNB];
#pragma unroll
    for (int t = 0; t < KNB; t++) { bd[t] = 3.4e38f; bi[t] = 0; }
    float worst = 3.4e38f; int wpos = 0;

    for (int t0 = 0; t0 < NN; t0 += 2048) {
        __syncthreads();
        for (int e = tid; e < 2048; e += 256) {
            int j = t0 + e;
            float x = base[j*3+0], y = base[j*3+1], z = base[j*3+2];
            sx[e] = x; sy[e] = y; sz[e] = z; ss[e] = x*x + y*y + z*z;
        }
        __syncthreads();
#pragma unroll 4
        for (int e = par; e < 2048; e += 4) {
            float d = qs + ss[e] - 2.0f*(qx*sx[e] + qy*sy[e] + qz*sz[e]);
            if (d < worst) {
                int j = t0 + e;
#pragma unroll
                for (int t = 0; t < KNB; t++) if (t == wpos) { bd[t] = d; bi[t] = j; }
                worst = -3.4e38f;
#pragma unroll
                for (int t = 0; t < KNB; t++) if (bd[t] > worst) { worst = bd[t]; wpos = t; }
            }
        }
    }
    __syncthreads();
    if (par != 0) {
        int slot = qloc*3 + (par-1);
#pragma unroll
        for (int t = 0; t < KNB; t++) { sMD[slot*KNB+t] = bd[t]; sMI[slot*KNB+t] = bi[t]; }
    }
    __syncthreads();
    if (par == 0) {
#pragma unroll 1
        for (int m = 0; m < 3; m++) {
            int slot = qloc*3 + m;
#pragma unroll
            for (int t = 0; t < KNB; t++) {
                float d = sMD[slot*KNB+t];
                if (d < worst) {
                    int j = sMI[slot*KNB+t];
#pragma unroll
                    for (int u = 0; u < KNB; u++) if (u == wpos) { bd[u] = d; bi[u] = j; }
                    worst = -3.4e38f;
#pragma unroll
                    for (int u = 0; u < KNB; u++) if (bd[u] > worst) { worst = bd[u]; wpos = u; }
                }
            }
        }
        int q = b*NN + n;
#pragma unroll
        for (int t = 0; t < KNB; t++) g_idx[q*KNB + t] = bi[t];
    }
}

// ---------------- QKV via mma.sync (R5-proven, unchanged) ----------------
__device__ __forceinline__ void qkv_stage_w(char* sm, const float* __restrict__ Wg) {
    char* hiP = sm + 2*PLANE;
    char* loP = sm + 3*PLANE;
    const int tid = threadIdx.x;
#pragma unroll
    for (int e = tid; e < 8192; e += 512) {
        int n = e >> 6, kp = e & 63;
        float2 wv = *(const float2*)&Wg[n*128 + 2*kp];
        split_lin(hiP, loP, n*BSTR + kp*4, wv.x, wv.y);
    }
}
__device__ __forceinline__ void qkv_gemm(char* sm, float acc[8][4]) {
    const int lane = threadIdx.x & 31, w = threadIdx.x >> 5;
    const int r0 = (w & 7) * 16, n0 = (w >> 3) * 64;
    u32 xb = cvta_s(sm);
    u32 wb = cvta_s(sm + 2*PLANE);
    const u32 aoff = (u32)(r0 + (lane & 15)) * BSTR + (lane >> 4) * 16;
    const u32 boff = (u32)(n0 + ((lane & 16) >> 1) + (lane & 7)) * BSTR
                   + ((lane >> 3) & 1) * 16;
#pragma unroll
    for (int nt = 0; nt < 8; nt++)
#pragma unroll
        for (int i = 0; i < 4; i++) acc[nt][i] = 0.0f;
#pragma unroll 2
    for (int kc = 0; kc < 128; kc += 16) {
        u32 ah[4], al[4], bhm[4][4], blm[4][4];
        ldsm4(xb + aoff + kc*2,         ah);
        ldsm4(xb + PLANE + aoff + kc*2, al);
#pragma unroll
        for (int p = 0; p < 4; p++) {
            ldsm4(wb + boff + p*16*BSTR + kc*2,         bhm[p]);
            ldsm4(wb + PLANE + boff + p*16*BSTR + kc*2, blm[p]);
        }
#pragma unroll
        for (int p = 0; p < 4; p++) {
#pragma unroll
            for (int h = 0; h < 2; h++) {
                const int nt = 2*p + h;
                mma_bf16(acc[nt], al, bhm[p][2*h], bhm[p][2*h+1]);
                mma_bf16(acc[nt], ah, blm[p][2*h], blm[p][2*h+1]);
                mma_bf16(acc[nt], ah, bhm[p][2*h], bhm[p][2*h+1]);
            }
        }
    }
}
__global__ __launch_bounds__(512, 1) void qkv_kernel(const float* __restrict__ feat,
                                                     const float* __restrict__ Wq,
                                                     const float* __restrict__ Wk,
                                                     const float* __restrict__ Wv)
{
    extern __shared__ char sm[];
    const int tid = threadIdx.x;
    const int lane = tid & 31, w = tid >> 5;
    const int r0 = (w & 7) * 16, n0 = (w >> 3) * 64;
    const int g = lane >> 2, ct = lane & 3;
    size_t row0 = (size_t)blockIdx.x * 128;

#pragma unroll
    for (int e = tid; e < 8192; e += 512) {
        int r = e >> 6, kp = e & 63;
        float2 f = *(const float2*)&feat[(row0 + r)*128 + 2*kp];
        split_lin(sm, sm + PLANE, r*BSTR + kp*4, f.x, f.y);
    }
    const float* Ws[3] = {Wq, Wk, Wv};
    float* Gs[3] = {g_q, g_k, g_v};
#pragma unroll 1
    for (int m = 0; m < 3; m++) {
        __syncthreads();
        qkv_stage_w(sm, Ws[m]);
        __syncthreads();
        float acc[8][4];
        qkv_gemm(sm, acc);
        float* dst = Gs[m] + row0*128;
#pragma unroll
        for (int nt = 0; nt < 8; nt++) {
            int ra = r0 + g;
            int ca = n0 + nt*8 + 2*ct;
            *(float2*)&dst[(size_t)ra*128 + ca]     = make_float2(acc[nt][0], acc[nt][1]);
            *(float2*)&dst[(size_t)(ra+8)*128 + ca] = make_float2(acc[nt][2], acc[nt][3]);
        }
    }
}

// ---------------- main kernel GEMM: 64x128x128 double-split bf16, 2-pass over W planes ----------------
// 8 warps: warp w -> rows 16*(w&3), cols 64*(w>>2). acc persists across both passes.
__device__ __forceinline__ void stage_wplane(char* sm, const u32* __restrict__ plane) {
    float4* dst = (float4*)(sm + OFF_W);
    const float4* src = (const float4*)plane;
#pragma unroll
    for (int e = threadIdx.x; e < 2176; e += 256) dst[e] = src[e];
}
__device__ __forceinline__ void gemm2pass(char* sm, const u32* __restrict__ whi,
                                          const u32* __restrict__ wlo, float acc[8][4]) {
    const int lane = threadIdx.x & 31, w = threadIdx.x >> 5;
    const int r0 = (w & 3) * 16, n0 = (w >> 2) * 64;
    const u32 sb = cvta_s(sm);
    const u32 aoff = (u32)(r0 + (lane & 15)) * BSTR + (lane >> 4) * 16;
    const u32 boff = (u32)OFF_W + (u32)(n0 + ((lane & 16) >> 1) + (lane & 7)) * BSTR
                   + ((lane >> 3) & 1) * 16;
#pragma unroll
    for (int nt = 0; nt < 8; nt++)
#pragma unroll
        for (int i = 0; i < 4; i++) acc[nt][i] = 0.0f;

    __syncthreads();                 // A writes done; previous W readers done
    stage_wplane(sm, whi);
    __syncthreads();
#pragma unroll 2
    for (int kc = 0; kc < 128; kc += 16) {   // pass1: al*bh + ah*bh
        u32 ah[4], al[4], bm[4][4];
        ldsm4(sb + aoff + kc*2,          ah);
        ldsm4(sb + APLANE + aoff + kc*2, al);
#pragma unroll
        for (int p = 0; p < 4; p++) ldsm4(sb + boff + p*16*BSTR + kc*2, bm[p]);
#pragma unroll
        for (int p = 0; p < 4; p++)
#pragma unroll
            for (int h = 0; h < 2; h++) {
                const int nt = 2*p + h;
                mma_bf16(acc[nt], al, bm[p][2*h], bm[p][2*h+1]);
                mma_bf16(acc[nt], ah, bm[p][2*h], bm[p][2*h+1]);
            }
    }
    __syncthreads();
    stage_wplane(sm, wlo);
    __syncthreads();
#pragma unroll 2
    for (int kc = 0; kc < 128; kc += 16) {   // pass2: ah*bl
        u32 ah[4], bm[4][4];
        ldsm4(sb + aoff + kc*2, ah);
#pragma unroll
        for (int p = 0; p < 4; p++) ldsm4(sb + boff + p*16*BSTR + kc*2, bm[p]);
#pragma unroll
        for (int p = 0; p < 4; p++)
#pragma unroll
            for (int h = 0; h < 2; h++)
                mma_bf16(acc[2*p+h], ah, bm[p][2*h], bm[p][2*h+1]);
    }
    __syncthreads();                 // all reads of A/W done before epilogue overwrites A
}

// ---------------- fused main kernel: 4 queries (64 pair-rows), 256 threads, 2 blocks/SM ----------------
__global__ __launch_bounds__(256, 2) void main_kernel(const float* __restrict__ xyz,
                                                      const float* __restrict__ pb2,
                                                      const float* __restrict__ ab2,
                                                      const float* __restrict__ Wout,
                                                      float* __restrict__ out)
{
    extern __shared__ char sm[];
    char* aHi = sm + OFF_AHI;
    char* aLo = sm + OFF_ALO;
    float* sVp  = (float*)(sm + OFF_VP);    // [64][132]
    float* sQ   = (float*)(sm + OFF_Q);     // [4][128]
    float* sOut = (float*)(sm + OFF_OUT);   // [4][128]
    float* sNx  = (float*)(sm + OFF_NX);
    float* sNy  = (float*)(sm + OFF_NY);
    float* sNz  = (float*)(sm + OFF_NZ);
    float* sQxyz= (float*)(sm + OFF_QXYZ);
    int*   sIdx = (int*)(sm + OFF_IDX);

    const int tid = threadIdx.x;
    const int lane = tid & 31, w = tid >> 5;
    const int r0 = (w & 3) * 16, n0 = (w >> 2) * 64;
    const int qi = w & 3;
    const int g = lane >> 2, ct = lane & 3;
    const int g0 = blockIdx.x * 4;
    const int b  = g0 >> 13;
    const int n0q = g0 & (NN - 1);
    const size_t bN = (size_t)b * NN;
    const float* xb = xyz + bN * 3;

    if (tid < 64) sIdx[tid] = g_idx[(size_t)g0 * KNB + tid];
    if (tid < 12) sQxyz[tid] = xb[(size_t)n0q * 3 + tid];
    for (int e = tid; e < 512; e += 256) sQ[e] = g_q[(size_t)g0 * 128 + e];
    __syncthreads();
    if (tid < 64) {
        int j = sIdx[tid];
        sNx[tid] = xb[j*3+0]; sNy[tid] = xb[j*3+1]; sNz[tid] = xb[j*3+2];
    }
    __syncthreads();

    // pos hidden = relu(rel @ pW1f^T + pb1f) -> A planes (64 rows)
#pragma unroll
    for (int e = tid; e < 4096; e += 256) {
        int rr = e >> 6, kp = e & 63;
        int o0 = 2*kp, o1 = o0 + 1;
        int qr = rr >> 4;
        float rx = sNx[rr] - sQxyz[qr*3+0];
        float ry = sNy[rr] - sQxyz[qr*3+1];
        float rz = sNz[rr] - sQxyz[qr*3+2];
        float h0 = fmaf(rx, g_pW1f[o0*3+0], fmaf(ry, g_pW1f[o0*3+1], fmaf(rz, g_pW1f[o0*3+2], g_pb1f[o0])));
        float h1 = fmaf(rx, g_pW1f[o1*3+0], fmaf(ry, g_pW1f[o1*3+1], fmaf(rz, g_pW1f[o1*3+2], g_pb1f[o1])));
        split_lin(aHi, aLo, rr*BSTR + kp*4, fmaxf(h0, 0.f), fmaxf(h1, 0.f));
    }

    // GEMM1: pos = hidden @ pW2^T ; epilogue: t -> A planes, vp -> sVp
    {
        float acc[8][4];
        gemm2pass(sm, g_wpl[0][0], g_wpl[0][1], acc);
#pragma unroll
        for (int nt = 0; nt < 8; nt++) {
            int ca = n0 + nt*8 + 2*ct;
            int ra0 = r0 + g, ra1 = ra0 + 8;
            float pb0 = __ldg(&pb2[ca]), pb1 = __ldg(&pb2[ca+1]);
            float p00 = acc[nt][0] + pb0, p01 = acc[nt][1] + pb1;
            float p10 = acc[nt][2] + pb0, p11 = acc[nt][3] + pb1;
            int j0 = sIdx[ra0], j1 = sIdx[ra1];
            float2 qv = *(const float2*)&sQ[qi*128 + ca];
            float2 k0 = *(const float2*)&g_k[(bN + j0)*128 + ca];
            float2 v0 = *(const float2*)&g_v[(bN + j0)*128 + ca];
            float2 k1 = *(const float2*)&g_k[(bN + j1)*128 + ca];
            float2 v1 = *(const float2*)&g_v[(bN + j1)*128 + ca];
            *(float2*)&sVp[ra0*132 + ca] = make_float2(v0.x + p00, v0.y + p01);
            *(float2*)&sVp[ra1*132 + ca] = make_float2(v1.x + p10, v1.y + p11);
            split_lin(aHi, aLo, ra0*BSTR + ca*2, qv.x - k0.x + p00, qv.y - k0.y + p01);
            split_lin(aHi, aLo, ra1*BSTR + ca*2, qv.x - k1.x + p10, qv.y - k1.y + p11);
        }
    }

    // GEMM2: h = relu(t @ aW1f^T + ab1f) -> A planes
    {
        float acc[8][4];
        gemm2pass(sm, g_wpl[1][0], g_wpl[1][1], acc);
#pragma unroll
        for (int nt = 0; nt < 8; nt++) {
            int ca = n0 + nt*8 + 2*ct;
            int ra0 = r0 + g, ra1 = ra0 + 8;
            float b0 = __ldg(&g_ab1f[ca]), b1 = __ldg(&g_ab1f[ca+1]);
            split_lin(aHi, aLo, ra0*BSTR + ca*2,
                      fmaxf(acc[nt][0] + b0, 0.f), fmaxf(acc[nt][1] + b1, 0.f));
            split_lin(aHi, aLo, ra1*BSTR + ca*2,
                      fmaxf(acc[nt][2] + b0, 0.f), fmaxf(acc[nt][3] + b1, 0.f));
        }
    }

    // GEMM3: logits = h @ aW2^T + ab2 ; register softmax over K=16; weighted vp sum
    {
        float acc[8][4];
        gemm2pass(sm, g_wpl[2][0], g_wpl[2][1], acc);
#pragma unroll
        for (int nt = 0; nt < 8; nt++) {
            int ca = n0 + nt*8 + 2*ct;
            int ra0 = r0 + g, ra1 = ra0 + 8;
            float b0 = __ldg(&ab2[ca]), b1 = __ldg(&ab2[ca+1]);
            float l00 = acc[nt][0] + b0, l01 = acc[nt][1] + b1;
            float l10 = acc[nt][2] + b0, l11 = acc[nt][3] + b1;
            float m0 = redmax(fmaxf(l00, l10));
            float m1 = redmax(fmaxf(l01, l11));
            float e00 = __expf(l00 - m0), e10 = __expf(l10 - m0);
            float e01 = __expf(l01 - m1), e11 = __expf(l11 - m1);
            float s0 = redsum(e00 + e10);
            float s1 = redsum(e01 + e11);
            float2 vpa = *(const float2*)&sVp[ra0*132 + ca];
            float2 vpb = *(const float2*)&sVp[ra1*132 + ca];
            float w0 = redsum(fmaf(e00, vpa.x, e10 * vpb.x));
            float w1 = redsum(fmaf(e01, vpa.y, e11 * vpb.y));
            if (g == 0)
                *(float2*)&sOut[qi*128 + ca] = make_float2(w0 / s0, w1 / s1);
        }
        __syncthreads();
    }

    // final: out = sOut @ Wout^T (4x128 rows). Wout chunks staged in W area (fp32 [128][17]).
    {
        float* sWs = (float*)(sm + OFF_W);
        float facc[2] = {0.f, 0.f};
        for (int kc = 0; kc < 128; kc += 16) {
            __syncthreads();
#pragma unroll
            for (int e = tid; e < 2048; e += 256) {
                int o = e >> 4, k = e & 15;
                sWs[o*17 + k] = Wout[o*128 + kc + k];
            }
            __syncthreads();
#pragma unroll
            for (int k = 0; k < 16; k++) {
#pragma unroll
                for (int u = 0; u < 2; u++) {
                    int it = tid + u*256;
                    int qr = it >> 7, o = it & 127;
                    facc[u] = fmaf(sOut[qr*128 + kc + k], sWs[o*17 + k], facc[u]);
                }
            }
        }
#pragma unroll
        for (int u = 0; u < 2; u++) {
            int it = tid + u*256;
            int qr = it >> 7, o = it & 127;
            out[((size_t)g0 + qr) * 128 + o] = facc[u];
        }
    }
}

// ---------------- launch ----------------
extern "C" void kernel_launch(void* const* d_in, const int* in_sizes, int n_in,
                              void* d_out, int out_size)
{
    const float* xyz   = (const float*)d_in[0];
    const float* feat  = (const float*)d_in[1];
    const float* Wq    = (const float*)d_in[2];
    const float* Wk    = (const float*)d_in[3];
    const float* Wv    = (const float*)d_in[4];
    const float* pW1   = (const float*)d_in[5];
    const float* pb1   = (const float*)d_in[6];
    const float* pg    = (const float*)d_in[7];
    const float* pbeta = (const float*)d_in[8];
    const float* pmean = (const float*)d_in[9];
    const float* pvar  = (const float*)d_in[10];
    const float* pW2   = (const float*)d_in[11];
    const float* pb2   = (const float*)d_in[12];
    const float* aW1   = (const float*)d_in[13];
    const float* ab1   = (const float*)d_in[14];
    const float* ag    = (const float*)d_in[15];
    const float* abeta = (const float*)d_in[16];
    const float* amean = (const float*)d_in[17];
    const float* avar  = (const float*)d_in[18];
    const float* aW2   = (const float*)d_in[19];
    const float* ab2   = (const float*)d_in[20];
    const float* Wout  = (const float*)d_in[21];
    float* out = (float*)d_out;

    cudaFuncSetAttribute((const void*)knn_kernel,
                         cudaFuncAttributeMaxDynamicSharedMemorySize, KNN_SMEM);
    cudaFuncSetAttribute((const void*)qkv_kernel,
                         cudaFuncAttributeMaxDynamicSharedMemorySize, QKV_SMEM);
    cudaFuncSetAttribute((const void*)main_kernel,
                         cudaFuncAttributeMaxDynamicSharedMemorySize, MAIN_SMEM);

    fold_kernel<<<1, 512>>>(pW1, pb1, pg, pbeta, pmean, pvar,
                            aW1, ab1, ag, abeta, amean, avar, pW2, aW2);
    knn_kernel<<<(BB*NN)/64, 256, KNN_SMEM>>>(xyz);
    qkv_kernel<<<(BB*NN)/128, 512, QKV_SMEM>>>(feat, Wq, Wk, Wv);
    main_kernel<<<(BB*NN)/4, 256, MAIN_SMEM>>>(xyz, pb2, ab2, Wout, out);
}

// round 9
// speedup vs baseline: 1.1432x; 1.1432x over previous
#include <cuda_runtime.h>
#include <cuda_bf16.h>
#include <cstdint>
#include <math.h>

typedef unsigned int u32;
typedef unsigned long long u64;

#define BB 2
#define NN 8192
#define CC 128
#define KNB 16
#define EPSF 1e-5f

// bf16 plane row stride: 136 elems = 272 bytes (ldmatrix conflict-free padding)
#define BSTR 272
#define PLANE 34816     // 128-row bf16 plane bytes
#define APLANE 17408    // 64-row bf16 plane bytes

// ---- main kernel smem offsets (512 threads, 128 pair-rows) ----
#define M_ALO 34816
#define M_W   69632          // hi plane; lo at M_W+PLANE
#define M_VP  139264         // [128][132] fp32
#define M_Q   206848         // [8][128] fp32
#define M_OUT 210944         // [8][128] fp32
#define M_NX  215040
#define M_NY  215552
#define M_NZ  216064
#define M_QXYZ 216576
#define M_IDX  216704
#define MAIN_SMEM 217216

// ---- qkv kernel smem (256 threads, 64 rows) ----
#define Q_W 34816            // hi at 34816, lo at 69632
#define QKV_SMEM 104448

// ---- knn kernel smem ----
#define KBUFCAP 24
#define KWIN 64
#define KNN_TILEB 32768      // 2048 x float4
#define KNN_SMEM (KNN_TILEB + 256*KBUFCAP*8)   // 32KB + 48KB = 80KB

// ---------------- device scratch ----------------
__device__ float g_q[BB*NN*CC];
__device__ float g_k[BB*NN*CC];
__device__ float g_v[BB*NN*CC];
__device__ int   g_idx[BB*NN*KNB];
__device__ float g_pW1f[CC*3];
__device__ float g_pb1f[CC];
__device__ float g_ab1f[CC];
// pre-split bf16 hi/lo planes (BSTR layout): 0=pW2 1=aW1f 2=aW2 3=Wq 4=Wk 5=Wv
__device__ __align__(16) u32 g_wpl[6][2][8704];

// ---------------- helpers ----------------
__device__ __forceinline__ u32 cvta_s(const void* p) {
    return (u32)__cvta_generic_to_shared(p);
}
__device__ __forceinline__ u32 packbf(float x, float y) {
    u32 r; asm("cvt.rn.bf16x2.f32 %0, %1, %2;" : "=r"(r) : "f"(y), "f"(x)); return r;
}
__device__ __forceinline__ float bhi(float v) {
    return __bfloat162float(__float2bfloat16(v));
}
__device__ __forceinline__ void split_lin(char* hiP, char* loP, int off, float x, float y) {
    float hx = bhi(x), hy = bhi(y);
    *(u32*)(hiP + off) = packbf(hx, hy);
    *(u32*)(loP + off) = packbf(x - hx, y - hy);
}
__device__ __forceinline__ void ldsm4(u32 addr, u32 r[4]) {
    asm volatile("ldmatrix.sync.aligned.m8n8.x4.shared.b16 {%0,%1,%2,%3},[%4];"
                 : "=r"(r[0]), "=r"(r[1]), "=r"(r[2]), "=r"(r[3]) : "r"(addr));
}
__device__ __forceinline__ void mma_bf16(float c[4], const u32 a[4], u32 b0, u32 b1) {
    asm volatile("mma.sync.aligned.m16n8k16.row.col.f32.bf16.bf16.f32 "
                 "{%0,%1,%2,%3},{%4,%5,%6,%7},{%8,%9},{%0,%1,%2,%3};"
                 : "+f"(c[0]), "+f"(c[1]), "+f"(c[2]), "+f"(c[3])
                 : "r"(a[0]), "r"(a[1]), "r"(a[2]), "r"(a[3]), "r"(b0), "r"(b1));
}
__device__ __forceinline__ float redmax(float v) {
    v = fmaxf(v, __shfl_xor_sync(0xffffffffu, v, 4));
    v = fmaxf(v, __shfl_xor_sync(0xffffffffu, v, 8));
    v = fmaxf(v, __shfl_xor_sync(0xffffffffu, v, 16));
    return v;
}
__device__ __forceinline__ float redsum(float v) {
    v += __shfl_xor_sync(0xffffffffu, v, 4);
    v += __shfl_xor_sync(0xffffffffu, v, 8);
    v += __shfl_xor_sync(0xffffffffu, v, 16);
    return v;
}
__device__ __forceinline__ void topk_insert(float d, int j, float (&bd)[KNB], int (&bi)[KNB],
                                            float &worst, int &wpos) {
#pragma unroll
    for (int t = 0; t < KNB; t++) if (t == wpos) { bd[t] = d; bi[t] = j; }
    worst = -3.4e38f;
#pragma unroll
    for (int t = 0; t < KNB; t++) if (bd[t] > worst) { worst = bd[t]; wpos = t; }
}

// ---------------- fold BN + pre-split all six 128x128 weights ----------------
__global__ void fold_kernel(const float* __restrict__ pW1, const float* __restrict__ pb1,
                            const float* __restrict__ pg,  const float* __restrict__ pbeta,
                            const float* __restrict__ pmean,const float* __restrict__ pvar,
                            const float* __restrict__ aW1, const float* __restrict__ ab1,
                            const float* __restrict__ ag,  const float* __restrict__ abeta,
                            const float* __restrict__ amean,const float* __restrict__ avar,
                            const float* __restrict__ pW2, const float* __restrict__ aW2,
                            const float* __restrict__ Wq,  const float* __restrict__ Wk,
                            const float* __restrict__ Wv)
{
    int tid = threadIdx.x;      // 512 threads
    if (tid < CC) {
        int o = tid;
        float s = pg[o] * rsqrtf(pvar[o] + EPSF);
        g_pW1f[o*3+0] = pW1[o*3+0] * s;
        g_pW1f[o*3+1] = pW1[o*3+1] * s;
        g_pW1f[o*3+2] = pW1[o*3+2] * s;
        g_pb1f[o] = pb1[o]*s + pbeta[o] - pmean[o]*s;
        float sa = ag[o] * rsqrtf(avar[o] + EPSF);
        g_ab1f[o] = ab1[o]*sa + abeta[o] - amean[o]*sa;
    }
    for (int e = tid; e < 6*8192; e += 512) {
        int widx = e >> 13, idx = e & 8191;
        int o = idx >> 6, kp = idx & 63;
        const float* W;
        float sc = 1.0f;
        switch (widx) {
            case 0: W = pW2; break;
            case 1: W = aW1; sc = ag[o] * rsqrtf(avar[o] + EPSF); break;
            case 2: W = aW2; break;
            case 3: W = Wq; break;
            case 4: W = Wk; break;
            default: W = Wv; break;
        }
        float w0 = W[o*128 + 2*kp] * sc, w1 = W[o*128 + 2*kp + 1] * sc;
        float h0 = bhi(w0), h1 = bhi(w1);
        g_wpl[widx][0][o*68 + kp] = packbf(h0, h1);
        g_wpl[widx][1][o*68 + kp] = packbf(w0 - h0, w1 - h1);
    }
}

// ---------------- KNN v2: buffered candidates, uniform compaction ----------------
// 256 blocks x 256 threads; 4 threads/query; thread scans 2048 candidates (stride 4).
__global__ __launch_bounds__(256, 2) void knn_kernel(const float* __restrict__ xyz)
{
    extern __shared__ char ksm[];
    float4* sT = (float4*)ksm;                       // [2048] tile (x,y,z,|p|^2)
    u64* sBuf = (u64*)(ksm + KNN_TILEB);             // [256][KBUFCAP]
    // merge region overlays tile after scan:
    float* sMD = (float*)ksm;                        // 64*3*16 floats
    int*   sMI = (int*)ksm + 3072;                   // 64*3*16 ints

    const int tid = threadIdx.x;
    const int qloc = tid >> 2;
    const int par  = tid & 3;
    const int b = blockIdx.x >> 7;
    const int n = ((blockIdx.x & 127) << 6) + qloc;
    const float* base = xyz + (size_t)b * NN * 3;

    const float qx = base[n*3+0], qy = base[n*3+1], qz = base[n*3+2];
    const float qs = qx*qx + qy*qy + qz*qz;

    float bd[KNB]; int bi[KNB];
#pragma unroll
    for (int t = 0; t < KNB; t++) { bd[t] = 3.4e38f; bi[t] = 0; }
    float worst = 3.4e38f; int wpos = 0;
    u64* myb = sBuf + tid * KBUFCAP;
    int cnt = 0;

    for (int t0 = 0; t0 < NN; t0 += 2048) {
        __syncthreads();
        for (int e = tid; e < 2048; e += 256) {
            int j = t0 + e;
            float x = base[j*3+0], y = base[j*3+1], z = base[j*3+2];
            sT[e] = make_float4(x, y, z, x*x + y*y + z*z);
        }
        __syncthreads();
        for (int wb = 0; wb < 2048; wb += KWIN) {
#pragma unroll 4
            for (int e = wb + par; e < wb + KWIN; e += 4) {
                float4 c = sT[e];
                float d = qs + c.w - 2.0f*(qx*c.x + qy*c.y + qz*c.z);
                if (d < worst) {
                    int j = t0 + e;
                    if (cnt < KBUFCAP) {
                        myb[cnt] = ((u64)__float_as_uint(d) << 32) | (u32)j;
                        cnt++;
                    } else {
                        topk_insert(d, j, bd, bi, worst, wpos);  // rare overflow fallback
                    }
                }
            }
            // uniform compaction point (loop length divergent per lane, bounded by cnt)
            for (int c = 0; c < cnt; c++) {
                u64 kj = myb[c];
                float d = __uint_as_float((u32)(kj >> 32));
                if (d < worst) topk_insert(d, (int)(u32)(kj & 0xFFFFFFFFu), bd, bi, worst, wpos);
            }
            cnt = 0;
        }
    }
    __syncthreads();   // done with tiles; reuse region for merge
    if (par != 0) {
        int slot = qloc*3 + (par-1);
#pragma unroll
        for (int t = 0; t < KNB; t++) { sMD[slot*KNB+t] = bd[t]; sMI[slot*KNB+t] = bi[t]; }
    }
    __syncthreads();
    if (par == 0) {
#pragma unroll 1
        for (int m = 0; m < 3; m++) {
            int slot = qloc*3 + m;
#pragma unroll
            for (int t = 0; t < KNB; t++) {
                float d = sMD[slot*KNB+t];
                if (d < worst) topk_insert(d, sMI[slot*KNB+t], bd, bi, worst, wpos);
            }
        }
        int q = b*NN + n;
#pragma unroll
        for (int t = 0; t < KNB; t++) g_idx[q*KNB + t] = bi[t];
    }
}

// ---------------- QKV: 64-row blocks, pre-split weights, 3-term single pass ----------------
__global__ __launch_bounds__(256, 2) void qkv_kernel(const float* __restrict__ feat)
{
    extern __shared__ char sm[];
    const int tid = threadIdx.x;
    const int lane = tid & 31, w = tid >> 5;
    const int r0 = (w & 3) * 16, n0 = (w >> 2) * 64;
    const int g = lane >> 2, ct = lane & 3;
    size_t row0 = (size_t)blockIdx.x * 64;

    // stage 64 feat rows split into hi/lo planes
#pragma unroll
    for (int e = tid; e < 4096; e += 256) {
        int r = e >> 6, kp = e & 63;
        float2 f = *(const float2*)&feat[(row0 + r)*128 + 2*kp];
        split_lin(sm, sm + APLANE, r*BSTR + kp*4, f.x, f.y);
    }

    const u32 xb = cvta_s(sm);
    const u32 wb = cvta_s(sm + Q_W);
    const u32 aoff = (u32)(r0 + (lane & 15)) * BSTR + (lane >> 4) * 16;
    const u32 boff = (u32)(n0 + ((lane & 16) >> 1) + (lane & 7)) * BSTR
                   + ((lane >> 3) & 1) * 16;
    float* Gs[3] = {g_q, g_k, g_v};

#pragma unroll 1
    for (int m = 0; m < 3; m++) {
        __syncthreads();
        {   // stage both weight planes (pure copy, 69632B)
            float4* dst = (float4*)(sm + Q_W);
            const float4* src = (const float4*)g_wpl[3 + m];
#pragma unroll
            for (int e = tid; e < 4352; e += 256) dst[e] = src[e];
        }
        __syncthreads();
        float acc[8][4];
#pragma unroll
        for (int nt = 0; nt < 8; nt++)
#pragma unroll
            for (int i = 0; i < 4; i++) acc[nt][i] = 0.0f;
#pragma unroll 2
        for (int kc = 0; kc < 128; kc += 16) {
            u32 ah[4], al[4], bhm[4][4], blm[4][4];
            ldsm4(xb + aoff + kc*2,          ah);
            ldsm4(xb + APLANE + aoff + kc*2, al);
#pragma unroll
            for (int p = 0; p < 4; p++) {
                ldsm4(wb + boff + p*16*BSTR + kc*2,         bhm[p]);
                ldsm4(wb + PLANE + boff + p*16*BSTR + kc*2, blm[p]);
            }
#pragma unroll
            for (int p = 0; p < 4; p++)
#pragma unroll
                for (int h = 0; h < 2; h++) {
                    const int nt = 2*p + h;
                    mma_bf16(acc[nt], al, bhm[p][2*h], bhm[p][2*h+1]);
                    mma_bf16(acc[nt], ah, blm[p][2*h], blm[p][2*h+1]);
                    mma_bf16(acc[nt], ah, bhm[p][2*h], bhm[p][2*h+1]);
                }
        }
        float* dst = Gs[m] + row0*128;
#pragma unroll
        for (int nt = 0; nt < 8; nt++) {
            int ra = r0 + g;
            int ca = n0 + nt*8 + 2*ct;
            *(float2*)&dst[(size_t)ra*128 + ca]     = make_float2(acc[nt][0], acc[nt][1]);
            *(float2*)&dst[(size_t)(ra+8)*128 + ca] = make_float2(acc[nt][2], acc[nt][3]);
        }
    }
}

// ---------------- main kernel GEMM: 128x128x128, pre-split W, 3-term single pass ----------------
// 16 warps: warp w -> rows 16*(w&7), cols 64*(w>>3). Ends with __syncthreads().
__device__ __forceinline__ void main_gemm(char* sm, const u32* __restrict__ wg, float acc[8][4]) {
    const int tid = threadIdx.x;
    __syncthreads();   // A writes done; previous W readers done
    {
        float4* dst = (float4*)(sm + M_W);
        const float4* src = (const float4*)wg;
#pragma unroll
        for (int e = tid; e < 4352; e += 512) dst[e] = src[e];
    }
    __syncthreads();
    const int lane = tid & 31, w = tid >> 5;
    const int r0 = (w & 7) * 16, n0 = (w >> 3) * 64;
    const u32 xb = cvta_s(sm);
    const u32 wb = cvta_s(sm + M_W);
    const u32 aoff = (u32)(r0 + (lane & 15)) * BSTR + (lane >> 4) * 16;
    const u32 boff = (u32)(n0 + ((lane & 16) >> 1) + (lane & 7)) * BSTR
                   + ((lane >> 3) & 1) * 16;
#pragma unroll
    for (int nt = 0; nt < 8; nt++)
#pragma unroll
        for (int i = 0; i < 4; i++) acc[nt][i] = 0.0f;
#pragma unroll 2
    for (int kc = 0; kc < 128; kc += 16) {
        u32 ah[4], al[4], bhm[4][4], blm[4][4];
        ldsm4(xb + aoff + kc*2,         ah);
        ldsm4(xb + PLANE + aoff + kc*2, al);
#pragma unroll
        for (int p = 0; p < 4; p++) {
            ldsm4(wb + boff + p*16*BSTR + kc*2,         bhm[p]);
            ldsm4(wb + PLANE + boff + p*16*BSTR + kc*2, blm[p]);
        }
#pragma unroll
        for (int p = 0; p < 4; p++)
#pragma unroll
            for (int h = 0; h < 2; h++) {
                const int nt = 2*p + h;
                mma_bf16(acc[nt], al, bhm[p][2*h], bhm[p][2*h+1]);
                mma_bf16(acc[nt], ah, blm[p][2*h], blm[p][2*h+1]);
                mma_bf16(acc[nt], ah, bhm[p][2*h], bhm[p][2*h+1]);
            }
    }
    __syncthreads();   // all reads done before epilogue overwrites A
}

// ---------------- fused main kernel: 8 queries (128 pair-rows), 512 threads ----------------
__global__ __launch_bounds__(512, 1) void main_kernel(const float* __restrict__ xyz,
                                                      const float* __restrict__ pb2,
                                                      const float* __restrict__ ab2,
                                                      const float* __restrict__ Wout,
                                                      float* __restrict__ out)
{
    extern __shared__ char sm[];
    char* aHi = sm;
    char* aLo = sm + M_ALO;
    float* sVp  = (float*)(sm + M_VP);
    float* sQ   = (float*)(sm + M_Q);
    float* sOut = (float*)(sm + M_OUT);
    float* sNx  = (float*)(sm + M_NX);
    float* sNy  = (float*)(sm + M_NY);
    float* sNz  = (float*)(sm + M_NZ);
    float* sQxyz= (float*)(sm + M_QXYZ);
    int*   sIdx = (int*)(sm + M_IDX);

    const int tid = threadIdx.x;
    const int lane = tid & 31, w = tid >> 5;
    const int r0 = (w & 7) * 16, n0 = (w >> 3) * 64;
    const int qi = w & 7;
    const int g = lane >> 2, ct = lane & 3;
    const int g0 = blockIdx.x * 8;
    const int b  = g0 >> 13;
    const int n0q = g0 & (NN - 1);
    const size_t bN = (size_t)b * NN;
    const float* xb = xyz + bN * 3;

    if (tid < 128) sIdx[tid] = g_idx[(size_t)g0 * KNB + tid];
    if (tid < 24)  sQxyz[tid] = xb[(size_t)n0q * 3 + tid];
    for (int e = tid; e < 1024; e += 512) sQ[e] = g_q[(size_t)g0 * 128 + e];
    __syncthreads();
    if (tid < 128) {
        int j = sIdx[tid];
        sNx[tid] = xb[j*3+0]; sNy[tid] = xb[j*3+1]; sNz[tid] = xb[j*3+2];
    }
    __syncthreads();

    // pos hidden = relu(rel @ pW1f^T + pb1f) -> A planes
#pragma unroll
    for (int e = tid; e < 8192; e += 512) {
        int rr = e >> 6, kp = e & 63;
        int o0 = 2*kp, o1 = o0 + 1;
        int qr = rr >> 4;
        float rx = sNx[rr] - sQxyz[qr*3+0];
        float ry = sNy[rr] - sQxyz[qr*3+1];
        float rz = sNz[rr] - sQxyz[qr*3+2];
        float h0 = fmaf(rx, g_pW1f[o0*3+0], fmaf(ry, g_pW1f[o0*3+1], fmaf(rz, g_pW1f[o0*3+2], g_pb1f[o0])));
        float h1 = fmaf(rx, g_pW1f[o1*3+0], fmaf(ry, g_pW1f[o1*3+1], fmaf(rz, g_pW1f[o1*3+2], g_pb1f[o1])));
        split_lin(aHi, aLo, rr*BSTR + kp*4, fmaxf(h0, 0.f), fmaxf(h1, 0.f));
    }

    // GEMM1: pos = hidden @ pW2^T ; epilogue: t -> A planes, vp -> sVp
    {
        float acc[8][4];
        main_gemm(sm, g_wpl[0][0], acc);
#pragma unroll
        for (int nt = 0; nt < 8; nt++) {
            int ca = n0 + nt*8 + 2*ct;
            int ra0 = r0 + g, ra1 = ra0 + 8;
            float pb0 = __ldg(&pb2[ca]), pb1 = __ldg(&pb2[ca+1]);
            float p00 = acc[nt][0] + pb0, p01 = acc[nt][1] + pb1;
            float p10 = acc[nt][2] + pb0, p11 = acc[nt][3] + pb1;
            int j0 = sIdx[ra0], j1 = sIdx[ra1];
            float2 qv = *(const float2*)&sQ[qi*128 + ca];
            float2 k0 = *(const float2*)&g_k[(bN + j0)*128 + ca];
            float2 v0 = *(const float2*)&g_v[(bN + j0)*128 + ca];
            float2 k1 = *(const float2*)&g_k[(bN + j1)*128 + ca];
            float2 v1 = *(const float2*)&g_v[(bN + j1)*128 + ca];
            *(float2*)&sVp[ra0*132 + ca] = make_float2(v0.x + p00, v0.y + p01);
            *(float2*)&sVp[ra1*132 + ca] = make_float2(v1.x + p10, v1.y + p11);
            split_lin(aHi, aLo, ra0*BSTR + ca*2, qv.x - k0.x + p00, qv.y - k0.y + p01);
            split_lin(aHi, aLo, ra1*BSTR + ca*2, qv.x - k1.x + p10, qv.y - k1.y + p11);
        }
    }

    // GEMM2: h = relu(t @ aW1f^T + ab1f)
    {
        float acc[8][4];
        main_gemm(sm, g_wpl[1][0], acc);
#pragma unroll
        for (int nt = 0; nt < 8; nt++) {
            int ca = n0 + nt*8 + 2*ct;
            int ra0 = r0 + g, ra1 = ra0 + 8;
            float b0 = __ldg(&g_ab1f[ca]), b1 = __ldg(&g_ab1f[ca+1]);
            split_lin(aHi, aLo, ra0*BSTR + ca*2,
                      fmaxf(acc[nt][0] + b0, 0.f), fmaxf(acc[nt][1] + b1, 0.f));
            split_lin(aHi, aLo, ra1*BSTR + ca*2,
                      fmaxf(acc[nt][2] + b0, 0.f), fmaxf(acc[nt][3] + b1, 0.f));
        }
    }

    // GEMM3: logits = h @ aW2^T + ab2 ; register softmax over K=16; weighted vp sum
    {
        float acc[8][4];
        main_gemm(sm, g_wpl[2][0], acc);
#pragma unroll
        for (int nt = 0; nt < 8; nt++) {
            int ca = n0 + nt*8 + 2*ct;
            int ra0 = r0 + g, ra1 = ra0 + 8;
            float b0 = __ldg(&ab2[ca]), b1 = __ldg(&ab2[ca+1]);
            float l00 = acc[nt][0] + b0, l01 = acc[nt][1] + b1;
            float l10 = acc[nt][2] + b0, l11 = acc[nt][3] + b1;
            float m0 = redmax(fmaxf(l00, l10));
            float m1 = redmax(fmaxf(l01, l11));
            float e00 = __expf(l00 - m0), e10 = __expf(l10 - m0);
            float e01 = __expf(l01 - m1), e11 = __expf(l11 - m1);
            float s0 = redsum(e00 + e10);
            float s1 = redsum(e01 + e11);
            float2 vpa = *(const float2*)&sVp[ra0*132 + ca];
            float2 vpb = *(const float2*)&sVp[ra1*132 + ca];
            float w0 = redsum(fmaf(e00, vpa.x, e10 * vpb.x));
            float w1 = redsum(fmaf(e01, vpa.y, e11 * vpb.y));
            if (g == 0)
                *(float2*)&sOut[qi*128 + ca] = make_float2(w0 / s0, w1 / s1);
        }
        __syncthreads();
    }

    // final: out = sOut @ Wout^T (8x128). Wout chunks staged in W area (fp32 [128][17]).
    {
        float* sWs = (float*)(sm + M_W);
        float facc[2] = {0.f, 0.f};
        for (int kc = 0; kc < 128; kc += 16) {
            __syncthreads();
#pragma unroll
            for (int e = tid; e < 2048; e += 512) {
                int o = e >> 4, k = e & 15;
                sWs[o*17 + k] = Wout[o*128 + kc + k];
            }
            __syncthreads();
#pragma unroll
            for (int k = 0; k < 16; k++) {
#pragma unroll
                for (int u = 0; u < 2; u++) {
                    int it = tid + u*512;
                    int qr = it >> 7, o = it & 127;
                    facc[u] = fmaf(sOut[qr*128 + kc + k], sWs[o*17 + k], facc[u]);
                }
            }
        }
#pragma unroll
        for (int u = 0; u < 2; u++) {
            int it = tid + u*512;
            int qr = it >> 7, o = it & 127;
            out[((size_t)g0 + qr) * 128 + o] = facc[u];
        }
    }
}

// ---------------- launch ----------------
extern "C" void kernel_launch(void* const* d_in, const int* in_sizes, int n_in,
                              void* d_out, int out_size)
{
    const float* xyz   = (const float*)d_in[0];
    const float* feat  = (const float*)d_in[1];
    const float* Wq    = (const float*)d_in[2];
    const float* Wk    = (const float*)d_in[3];
    const float* Wv    = (const float*)d_in[4];
    const float* pW1   = (const float*)d_in[5];
    const float* pb1   = (const float*)d_in[6];
    const float* pg    = (const float*)d_in[7];
    const float* pbeta = (const float*)d_in[8];
    const float* pmean = (const float*)d_in[9];
    const float* pvar  = (const float*)d_in[10];
    const float* pW2   = (const float*)d_in[11];
    const float* pb2   = (const float*)d_in[12];
    const float* aW1   = (const float*)d_in[13];
    const float* ab1   = (const float*)d_in[14];
    const float* ag    = (const float*)d_in[15];
    const float* abeta = (const float*)d_in[16];
    const float* amean = (const float*)d_in[17];
    const float* avar  = (const float*)d_in[18];
    const float* aW2   = (const float*)d_in[19];
    const float* ab2   = (const float*)d_in[20];
    const float* Wout  = (const float*)d_in[21];
    float* out = (float*)d_out;

    cudaFuncSetAttribute((const void*)knn_kernel,
                         cudaFuncAttributeMaxDynamicSharedMemorySize, KNN_SMEM);
    cudaFuncSetAttribute((const void*)qkv_kernel,
                         cudaFuncAttributeMaxDynamicSharedMemorySize, QKV_SMEM);
    cudaFuncSetAttribute((const void*)main_kernel,
                         cudaFuncAttributeMaxDynamicSharedMemorySize, MAIN_SMEM);

    fold_kernel<<<1, 512>>>(pW1, pb1, pg, pbeta, pmean, pvar,
                            aW1, ab1, ag, abeta, amean, avar,
                            pW2, aW2, Wq, Wk, Wv);
    knn_kernel<<<(BB*NN)/64, 256, KNN_SMEM>>>(xyz);
    qkv_kernel<<<(BB*NN)/64, 256, QKV_SMEM>>>(feat);
    main_kernel<<<(BB*NN)/8, 512, MAIN_SMEM>>>(xyz, pb2, ab2, Wout, out);
}

// round 10
// speedup vs baseline: 1.1909x; 1.0417x over previous
#include <cuda_runtime.h>
#include <cuda_bf16.h>
#include <cstdint>
#include <math.h>

typedef unsigned int u32;
typedef unsigned long long u64;

#define BB 2
#define NN 8192
#define CC 128
#define KNB 16
#define EPSF 1e-5f

// bf16 plane row stride: 136 elems = 272 bytes (ldmatrix conflict-free padding)
#define BSTR 272
#define PLANE 34816     // 128-row bf16 plane bytes
#define APLANE 17408    // 64-row bf16 plane bytes

// ---- main kernel smem offsets ----
#define M_ALO 34816
#define M_WB0 69632          // W plane buffer 0
#define M_WB1 104448         // W plane buffer 1
#define M_VP  139264         // [128][132] fp32 ; later Wout [128][129] fp32
#define M_Q   206848         // [8][128] fp32 ; later sOut overlay
#define M_NX  210944
#define M_NY  211456
#define M_NZ  211968
#define M_QXYZ 212480
#define M_IDX  212608
#define MAIN_SMEM 213120

// ---- qkv kernel smem (256 threads, 64 rows) ----
#define Q_W 34816            // hi at 34816, lo at 69632
#define QKV_SMEM 104448

// ---- knn kernel smem ----
#define KBUFCAP 24
#define KWIN 64
#define KNN_TILEB 32768
#define KNN_SMEM (KNN_TILEB + 256*KBUFCAP*8)

// ---------------- device scratch ----------------
__device__ float g_q[BB*NN*CC];
__device__ float g_k[BB*NN*CC];
__device__ float g_v[BB*NN*CC];
__device__ int   g_idx[BB*NN*KNB];
__device__ float g_pW1f[CC*3];
__device__ float g_pb1f[CC];
__device__ float g_ab1f[CC];
// pre-split bf16 hi/lo planes (BSTR layout): 0=pW2 1=aW1f 2=aW2 3=Wq 4=Wk 5=Wv
__device__ __align__(16) u32 g_wpl[6][2][8704];

// ---------------- helpers ----------------
__device__ __forceinline__ u32 cvta_s(const void* p) {
    return (u32)__cvta_generic_to_shared(p);
}
__device__ __forceinline__ u32 packbf(float x, float y) {
    u32 r; asm("cvt.rn.bf16x2.f32 %0, %1, %2;" : "=r"(r) : "f"(y), "f"(x)); return r;
}
__device__ __forceinline__ float bhi(float v) {
    return __bfloat162float(__float2bfloat16(v));
}
__device__ __forceinline__ void split_lin(char* hiP, char* loP, int off, float x, float y) {
    float hx = bhi(x), hy = bhi(y);
    *(u32*)(hiP + off) = packbf(hx, hy);
    *(u32*)(loP + off) = packbf(x - hx, y - hy);
}
__device__ __forceinline__ void ldsm4(u32 addr, u32 r[4]) {
    asm volatile("ldmatrix.sync.aligned.m8n8.x4.shared.b16 {%0,%1,%2,%3},[%4];"
                 : "=r"(r[0]), "=r"(r[1]), "=r"(r[2]), "=r"(r[3]) : "r"(addr));
}
__device__ __forceinline__ void mma_bf16(float c[4], const u32 a[4], u32 b0, u32 b1) {
    asm volatile("mma.sync.aligned.m16n8k16.row.col.f32.bf16.bf16.f32 "
                 "{%0,%1,%2,%3},{%4,%5,%6,%7},{%8,%9},{%0,%1,%2,%3};"
                 : "+f"(c[0]), "+f"(c[1]), "+f"(c[2]), "+f"(c[3])
                 : "r"(a[0]), "r"(a[1]), "r"(a[2]), "r"(a[3]), "r"(b0), "r"(b1));
}
__device__ __forceinline__ void cpasync16(u32 saddr, const void* g) {
    asm volatile("cp.async.cg.shared.global [%0], [%1], 16;" :: "r"(saddr), "l"(g));
}
__device__ __forceinline__ void cp_commit() {
    asm volatile("cp.async.commit_group;" ::: "memory");
}
template<int N>
__device__ __forceinline__ void cp_wait() {
    asm volatile("cp.async.wait_group %0;" :: "n"(N) : "memory");
}
__device__ __forceinline__ float redmax(float v) {
    v = fmaxf(v, __shfl_xor_sync(0xffffffffu, v, 4));
    v = fmaxf(v, __shfl_xor_sync(0xffffffffu, v, 8));
    v = fmaxf(v, __shfl_xor_sync(0xffffffffu, v, 16));
    return v;
}
__device__ __forceinline__ float redsum(float v) {
    v += __shfl_xor_sync(0xffffffffu, v, 4);
    v += __shfl_xor_sync(0xffffffffu, v, 8);
    v += __shfl_xor_sync(0xffffffffu, v, 16);
    return v;
}
__device__ __forceinline__ void topk_insert(float d, int j, float (&bd)[KNB], int (&bi)[KNB],
                                            float &worst, int &wpos) {
#pragma unroll
    for (int t = 0; t < KNB; t++) if (t == wpos) { bd[t] = d; bi[t] = j; }
    worst = -3.4e38f;
#pragma unroll
    for (int t = 0; t < KNB; t++) if (bd[t] > worst) { worst = bd[t]; wpos = t; }
}

// ---------------- fold BN + pre-split all six 128x128 weights ----------------
__global__ void fold_kernel(const float* __restrict__ pW1, const float* __restrict__ pb1,
                            const float* __restrict__ pg,  const float* __restrict__ pbeta,
                            const float* __restrict__ pmean,const float* __restrict__ pvar,
                            const float* __restrict__ aW1, const float* __restrict__ ab1,
                            const float* __restrict__ ag,  const float* __restrict__ abeta,
                            const float* __restrict__ amean,const float* __restrict__ avar,
                            const float* __restrict__ pW2, const float* __restrict__ aW2,
                            const float* __restrict__ Wq,  const float* __restrict__ Wk,
                            const float* __restrict__ Wv)
{
    int tid = threadIdx.x;
    if (tid < CC) {
        int o = tid;
        float s = pg[o] * rsqrtf(pvar[o] + EPSF);
        g_pW1f[o*3+0] = pW1[o*3+0] * s;
        g_pW1f[o*3+1] = pW1[o*3+1] * s;
        g_pW1f[o*3+2] = pW1[o*3+2] * s;
        g_pb1f[o] = pb1[o]*s + pbeta[o] - pmean[o]*s;
        float sa = ag[o] * rsqrtf(avar[o] + EPSF);
        g_ab1f[o] = ab1[o]*sa + abeta[o] - amean[o]*sa;
    }
    for (int e = tid; e < 6*8192; e += 512) {
        int widx = e >> 13, idx = e & 8191;
        int o = idx >> 6, kp = idx & 63;
        const float* W;
        float sc = 1.0f;
        switch (widx) {
            case 0: W = pW2; break;
            case 1: W = aW1; sc = ag[o] * rsqrtf(avar[o] + EPSF); break;
            case 2: W = aW2; break;
            case 3: W = Wq; break;
            case 4: W = Wk; break;
            default: W = Wv; break;
        }
        float w0 = W[o*128 + 2*kp] * sc, w1 = W[o*128 + 2*kp + 1] * sc;
        float h0 = bhi(w0), h1 = bhi(w1);
        g_wpl[widx][0][o*68 + kp] = packbf(h0, h1);
        g_wpl[widx][1][o*68 + kp] = packbf(w0 - h0, w1 - h1);
    }
}

// ---------------- KNN: buffered candidates, uniform compaction (R9) ----------------
__global__ __launch_bounds__(256, 2) void knn_kernel(const float* __restrict__ xyz)
{
    extern __shared__ char ksm[];
    float4* sT = (float4*)ksm;
    u64* sBuf = (u64*)(ksm + KNN_TILEB);
    float* sMD = (float*)ksm;
    int*   sMI = (int*)ksm + 3072;

    const int tid = threadIdx.x;
    const int qloc = tid >> 2;
    const int par  = tid & 3;
    const int b = blockIdx.x >> 7;
    const int n = ((blockIdx.x & 127) << 6) + qloc;
    const float* base = xyz + (size_t)b * NN * 3;

    const float qx = base[n*3+0], qy = base[n*3+1], qz = base[n*3+2];
    const float qs = qx*qx + qy*qy + qz*qz;

    float bd[KNB]; int bi[KNB];
#pragma unroll
    for (int t = 0; t < KNB; t++) { bd[t] = 3.4e38f; bi[t] = 0; }
    float worst = 3.4e38f; int wpos = 0;
    u64* myb = sBuf + tid * KBUFCAP;
    int cnt = 0;

    for (int t0 = 0; t0 < NN; t0 += 2048) {
        __syncthreads();
        for (int e = tid; e < 2048; e += 256) {
            int j = t0 + e;
            float x = base[j*3+0], y = base[j*3+1], z = base[j*3+2];
            sT[e] = make_float4(x, y, z, x*x + y*y + z*z);
        }
        __syncthreads();
        for (int wb = 0; wb < 2048; wb += KWIN) {
#pragma unroll 4
            for (int e = wb + par; e < wb + KWIN; e += 4) {
                float4 c = sT[e];
                float d = qs + c.w - 2.0f*(qx*c.x + qy*c.y + qz*c.z);
                if (d < worst) {
                    int j = t0 + e;
                    if (cnt < KBUFCAP) {
                        myb[cnt] = ((u64)__float_as_uint(d) << 32) | (u32)j;
                        cnt++;
                    } else {
                        topk_insert(d, j, bd, bi, worst, wpos);
                    }
                }
            }
            for (int c = 0; c < cnt; c++) {
                u64 kj = myb[c];
                float d = __uint_as_float((u32)(kj >> 32));
                if (d < worst) topk_insert(d, (int)(u32)(kj & 0xFFFFFFFFu), bd, bi, worst, wpos);
            }
            cnt = 0;
        }
    }
    __syncthreads();
    if (par != 0) {
        int slot = qloc*3 + (par-1);
#pragma unroll
        for (int t = 0; t < KNB; t++) { sMD[slot*KNB+t] = bd[t]; sMI[slot*KNB+t] = bi[t]; }
    }
    __syncthreads();
    if (par == 0) {
#pragma unroll 1
        for (int m = 0; m < 3; m++) {
            int slot = qloc*3 + m;
#pragma unroll
            for (int t = 0; t < KNB; t++) {
                float d = sMD[slot*KNB+t];
                if (d < worst) topk_insert(d, sMI[slot*KNB+t], bd, bi, worst, wpos);
            }
        }
        int q = b*NN + n;
#pragma unroll
        for (int t = 0; t < KNB; t++) g_idx[q*KNB + t] = bi[t];
    }
}

// ---------------- QKV: 64-row blocks, pre-split weights (R9) ----------------
__global__ __launch_bounds__(256, 2) void qkv_kernel(const float* __restrict__ feat)
{
    extern __shared__ char sm[];
    const int tid = threadIdx.x;
    const int lane = tid & 31, w = tid >> 5;
    const int r0 = (w & 3) * 16, n0 = (w >> 2) * 64;
    const int g = lane >> 2, ct = lane & 3;
    size_t row0 = (size_t)blockIdx.x * 64;

#pragma unroll
    for (int e = tid; e < 4096; e += 256) {
        int r = e >> 6, kp = e & 63;
        float2 f = *(const float2*)&feat[(row0 + r)*128 + 2*kp];
        split_lin(sm, sm + APLANE, r*BSTR + kp*4, f.x, f.y);
    }

    const u32 xb = cvta_s(sm);
    const u32 wb = cvta_s(sm + Q_W);
    const u32 aoff = (u32)(r0 + (lane & 15)) * BSTR + (lane >> 4) * 16;
    const u32 boff = (u32)(n0 + ((lane & 16) >> 1) + (lane & 7)) * BSTR
                   + ((lane >> 3) & 1) * 16;
    float* Gs[3] = {g_q, g_k, g_v};

#pragma unroll 1
    for (int m = 0; m < 3; m++) {
        __syncthreads();
        {
            float4* dst = (float4*)(sm + Q_W);
            const float4* src = (const float4*)g_wpl[3 + m];
#pragma unroll
            for (int e = tid; e < 4352; e += 256) dst[e] = src[e];
        }
        __syncthreads();
        float acc[8][4];
#pragma unroll
        for (int nt = 0; nt < 8; nt++)
#pragma unroll
            for (int i = 0; i < 4; i++) acc[nt][i] = 0.0f;
#pragma unroll 2
        for (int kc = 0; kc < 128; kc += 16) {
            u32 ah[4], al[4], bhm[4][4], blm[4][4];
            ldsm4(xb + aoff + kc*2,          ah);
            ldsm4(xb + APLANE + aoff + kc*2, al);
#pragma unroll
            for (int p = 0; p < 4; p++) {
                ldsm4(wb + boff + p*16*BSTR + kc*2,         bhm[p]);
                ldsm4(wb + PLANE + boff + p*16*BSTR + kc*2, blm[p]);
            }
#pragma unroll
            for (int p = 0; p < 4; p++)
#pragma unroll
                for (int h = 0; h < 2; h++) {
                    const int nt = 2*p + h;
                    mma_bf16(acc[nt], al, bhm[p][2*h], bhm[p][2*h+1]);
                    mma_bf16(acc[nt], ah, blm[p][2*h], blm[p][2*h+1]);
                    mma_bf16(acc[nt], ah, bhm[p][2*h], bhm[p][2*h+1]);
                }
        }
        float* dst = Gs[m] + row0*128;
#pragma unroll
        for (int nt = 0; nt < 8; nt++) {
            int ra = r0 + g;
            int ca = n0 + nt*8 + 2*ct;
            *(float2*)&dst[(size_t)ra*128 + ca]     = make_float2(acc[nt][0], acc[nt][1]);
            *(float2*)&dst[(size_t)(ra+8)*128 + ca] = make_float2(acc[nt][2], acc[nt][3]);
        }
    }
}

// ---------------- main kernel building blocks ----------------
// async-copy one 34816B weight plane into a smem buffer (all 512 threads), then commit
__device__ __forceinline__ void plane_cp(u32 dst, const u32* __restrict__ src) {
#pragma unroll
    for (int e = threadIdx.x; e < 2176; e += 512)
        cpasync16(dst + e*16, src + e*4);
    cp_commit();
}
// pass1: acc += al*bh + ah*bh  (hi W plane in buffer at smem addr wb)
__device__ __forceinline__ void mma_pass1(u32 xb, u32 wb, u32 aoff, u32 boff, float acc[8][4]) {
#pragma unroll 2
    for (int kc = 0; kc < 128; kc += 16) {
        u32 ah[4], al[4], bm[4][4];
        ldsm4(xb + aoff + kc*2,         ah);
        ldsm4(xb + PLANE + aoff + kc*2, al);
#pragma unroll
        for (int p = 0; p < 4; p++) ldsm4(wb + boff + p*16*BSTR + kc*2, bm[p]);
#pragma unroll
        for (int p = 0; p < 4; p++)
#pragma unroll
            for (int h = 0; h < 2; h++) {
                const int nt = 2*p + h;
                mma_bf16(acc[nt], al, bm[p][2*h], bm[p][2*h+1]);
                mma_bf16(acc[nt], ah, bm[p][2*h], bm[p][2*h+1]);
            }
    }
}
// pass2: acc += ah*bl  (lo W plane in buffer at smem addr wb)
__device__ __forceinline__ void mma_pass2(u32 xb, u32 wb, u32 aoff, u32 boff, float acc[8][4]) {
#pragma unroll 2
    for (int kc = 0; kc < 128; kc += 16) {
        u32 ah[4], bm[4][4];
        ldsm4(xb + aoff + kc*2, ah);
#pragma unroll
        for (int p = 0; p < 4; p++) ldsm4(wb + boff + p*16*BSTR + kc*2, bm[p]);
#pragma unroll
        for (int p = 0; p < 4; p++)
#pragma unroll
            for (int h = 0; h < 2; h++)
                mma_bf16(acc[2*p+h], ah, bm[p][2*h], bm[p][2*h+1]);
    }
}

// ---------------- fused main kernel: 8 queries (128 pair-rows), 512 threads ----------------
__global__ __launch_bounds__(512, 1) void main_kernel(const float* __restrict__ xyz,
                                                      const float* __restrict__ pb2,
                                                      const float* __restrict__ ab2,
                                                      const float* __restrict__ Wout,
                                                      float* __restrict__ out)
{
    extern __shared__ char sm[];
    char* aHi = sm;
    char* aLo = sm + M_ALO;
    float* sVp  = (float*)(sm + M_VP);
    float* sQ   = (float*)(sm + M_Q);
    float* sOut = (float*)(sm + M_Q);      // overlay: sQ dead after epilogue-1
    float* sNx  = (float*)(sm + M_NX);
    float* sNy  = (float*)(sm + M_NY);
    float* sNz  = (float*)(sm + M_NZ);
    float* sQxyz= (float*)(sm + M_QXYZ);
    int*   sIdx = (int*)(sm + M_IDX);

    const int tid = threadIdx.x;
    const int lane = tid & 31, w = tid >> 5;
    const int r0 = (w & 7) * 16, n0 = (w >> 3) * 64;
    const int qi = w & 7;
    const int g = lane >> 2, ct = lane & 3;
    const int g0 = blockIdx.x * 8;
    const int b  = g0 >> 13;
    const int n0q = g0 & (NN - 1);
    const size_t bN = (size_t)b * NN;
    const float* xb = xyz + bN * 3;
    const u32 sb = cvta_s(sm);
    const u32 wb0 = sb + M_WB0, wb1 = sb + M_WB1;
    const u32 aoff = (u32)(r0 + (lane & 15)) * BSTR + (lane >> 4) * 16;
    const u32 boff = (u32)(n0 + ((lane & 16) >> 1) + (lane & 7)) * BSTR
                   + ((lane >> 3) & 1) * 16;

    // kick off W plane prefetches for GEMM1 immediately
    plane_cp(wb0, g_wpl[0][0]);          // P0 = pW2.hi
    plane_cp(wb1, g_wpl[0][1]);          // P1 = pW2.lo

    if (tid < 128) sIdx[tid] = g_idx[(size_t)g0 * KNB + tid];
    if (tid < 24)  sQxyz[tid] = xb[(size_t)n0q * 3 + tid];
    for (int e = tid; e < 1024; e += 512) sQ[e] = g_q[(size_t)g0 * 128 + e];
    __syncthreads();
    if (tid < 128) {
        int j = sIdx[tid];
        sNx[tid] = xb[j*3+0]; sNy[tid] = xb[j*3+1]; sNz[tid] = xb[j*3+2];
    }
    __syncthreads();

    // pos hidden = relu(rel @ pW1f^T + pb1f) -> A planes (overlaps W prefetch)
#pragma unroll
    for (int e = tid; e < 8192; e += 512) {
        int rr = e >> 6, kp = e & 63;
        int o0 = 2*kp, o1 = o0 + 1;
        int qr = rr >> 4;
        float rx = sNx[rr] - sQxyz[qr*3+0];
        float ry = sNy[rr] - sQxyz[qr*3+1];
        float rz = sNz[rr] - sQxyz[qr*3+2];
        float h0 = fmaf(rx, g_pW1f[o0*3+0], fmaf(ry, g_pW1f[o0*3+1], fmaf(rz, g_pW1f[o0*3+2], g_pb1f[o0])));
        float h1 = fmaf(rx, g_pW1f[o1*3+0], fmaf(ry, g_pW1f[o1*3+1], fmaf(rz, g_pW1f[o1*3+2], g_pb1f[o1])));
        split_lin(aHi, aLo, rr*BSTR + kp*4, fmaxf(h0, 0.f), fmaxf(h1, 0.f));
    }
    cp_wait<1>();            // P0 arrived (P1 may be pending)
    __syncthreads();

    float acc[8][4];
#pragma unroll
    for (int nt = 0; nt < 8; nt++)
#pragma unroll
        for (int i = 0; i < 4; i++) acc[nt][i] = 0.0f;

    // ---- GEMM1: pos = hidden @ pW2^T ----
    mma_pass1(sb, wb0, aoff, boff, acc);
    __syncthreads();                         // buf0 reads done
    plane_cp(wb0, g_wpl[1][0]);              // P2 = aW1f.hi
    cp_wait<1>();                            // P1 done (P2 pending)
    __syncthreads();
    mma_pass2(sb, wb1, aoff, boff, acc);
    __syncthreads();                         // A reads + buf1 reads done
    plane_cp(wb1, g_wpl[1][1]);              // P3 = aW1f.lo
    // epilogue 1: pos+bias; gather k,v; t -> A planes; vp -> sVp
#pragma unroll
    for (int nt = 0; nt < 8; nt++) {
        int ca = n0 + nt*8 + 2*ct;
        int ra0 = r0 + g, ra1 = ra0 + 8;
        float pb0 = __ldg(&pb2[ca]), pb1 = __ldg(&pb2[ca+1]);
        float p00 = acc[nt][0] + pb0, p01 = acc[nt][1] + pb1;
        float p10 = acc[nt][2] + pb0, p11 = acc[nt][3] + pb1;
        int j0 = sIdx[ra0], j1 = sIdx[ra1];
        float2 qv = *(const float2*)&sQ[qi*128 + ca];
        float2 k0 = *(const float2*)&g_k[(bN + j0)*128 + ca];
        float2 v0 = *(const float2*)&g_v[(bN + j0)*128 + ca];
        float2 k1 = *(const float2*)&g_k[(bN + j1)*128 + ca];
        float2 v1 = *(const float2*)&g_v[(bN + j1)*128 + ca];
        *(float2*)&sVp[ra0*132 + ca] = make_float2(v0.x + p00, v0.y + p01);
        *(float2*)&sVp[ra1*132 + ca] = make_float2(v1.x + p10, v1.y + p11);
        split_lin(aHi, aLo, ra0*BSTR + ca*2, qv.x - k0.x + p00, qv.y - k0.y + p01);
        split_lin(aHi, aLo, ra1*BSTR + ca*2, qv.x - k1.x + p10, qv.y - k1.y + p11);
        acc[nt][0] = acc[nt][1] = acc[nt][2] = acc[nt][3] = 0.0f;
    }
    cp_wait<1>();                            // P2 done (P3 pending)
    __syncthreads();

    // ---- GEMM2: h = relu(t @ aW1f^T + ab1f) ----
    mma_pass1(sb, wb0, aoff, boff, acc);
    __syncthreads();
    plane_cp(wb0, g_wpl[2][0]);              // P4 = aW2.hi
    cp_wait<1>();                            // P3 done (P4 pending)
    __syncthreads();
    mma_pass2(sb, wb1, aoff, boff, acc);
    __syncthreads();
    plane_cp(wb1, g_wpl[2][1]);              // P5 = aW2.lo
#pragma unroll
    for (int nt = 0; nt < 8; nt++) {
        int ca = n0 + nt*8 + 2*ct;
        int ra0 = r0 + g, ra1 = ra0 + 8;
        float b0 = __ldg(&g_ab1f[ca]), b1 = __ldg(&g_ab1f[ca+1]);
        split_lin(aHi, aLo, ra0*BSTR + ca*2,
                  fmaxf(acc[nt][0] + b0, 0.f), fmaxf(acc[nt][1] + b1, 0.f));
        split_lin(aHi, aLo, ra1*BSTR + ca*2,
                  fmaxf(acc[nt][2] + b0, 0.f), fmaxf(acc[nt][3] + b1, 0.f));
        acc[nt][0] = acc[nt][1] = acc[nt][2] = acc[nt][3] = 0.0f;
    }
    cp_wait<1>();                            // P4 done (P5 pending)
    __syncthreads();

    // ---- GEMM3: logits = h @ aW2^T + ab2 ----
    mma_pass1(sb, wb0, aoff, boff, acc);
    cp_wait<0>();                            // P5 done
    __syncthreads();
    mma_pass2(sb, wb1, aoff, boff, acc);
    // softmax over K=16 rows per query; weighted vp sum -> sOut (overlay on sQ)
#pragma unroll
    for (int nt = 0; nt < 8; nt++) {
        int ca = n0 + nt*8 + 2*ct;
        int ra0 = r0 + g, ra1 = ra0 + 8;
        float b0 = __ldg(&ab2[ca]), b1 = __ldg(&ab2[ca+1]);
        float l00 = acc[nt][0] + b0, l01 = acc[nt][1] + b1;
        float l10 = acc[nt][2] + b0, l11 = acc[nt][3] + b1;
        float m0 = redmax(fmaxf(l00, l10));
        float m1 = redmax(fmaxf(l01, l11));
        float e00 = __expf(l00 - m0), e10 = __expf(l10 - m0);
        float e01 = __expf(l01 - m1), e11 = __expf(l11 - m1);
        float s0 = redsum(e00 + e10);
        float s1 = redsum(e01 + e11);
        float2 vpa = *(const float2*)&sVp[ra0*132 + ca];
        float2 vpb = *(const float2*)&sVp[ra1*132 + ca];
        float w0 = redsum(fmaf(e00, vpa.x, e10 * vpb.x));
        float w1 = redsum(fmaf(e01, vpa.y, e11 * vpb.y));
        if (g == 0)
            *(float2*)&sOut[qi*128 + ca] = make_float2(w0 / s0, w1 / s1);
    }
    __syncthreads();                         // sOut visible; sVp fully read

    // stage full Wout into sVp region as fp32 [128][129] (conflict-free)
    {
        float* sW = (float*)(sm + M_VP);
#pragma unroll
        for (int e = tid; e < 16384; e += 512)
            sW[(e >> 7)*129 + (e & 127)] = Wout[e];
        __syncthreads();
        float facc[2] = {0.f, 0.f};
#pragma unroll 8
        for (int k = 0; k < 128; k++) {
#pragma unroll
            for (int u = 0; u < 2; u++) {
                int it = tid + u*512;
                int qr = it >> 7, o = it & 127;
                facc[u] = fmaf(sOut[qr*128 + k], sW[o*129 + k], facc[u]);
            }
        }
#pragma unroll
        for (int u = 0; u < 2; u++) {
            int it = tid + u*512;
            int qr = it >> 7, o = it & 127;
            out[((size_t)g0 + qr) * 128 + o] = facc[u];
        }
    }
}

// ---------------- launch ----------------
extern "C" void kernel_launch(void* const* d_in, const int* in_sizes, int n_in,
                              void* d_out, int out_size)
{
    const float* xyz   = (const float*)d_in[0];
    const float* feat  = (const float*)d_in[1];
    const float* Wq    = (const float*)d_in[2];
    const float* Wk    = (const float*)d_in[3];
    const float* Wv    = (const float*)d_in[4];
    const float* pW1   = (const float*)d_in[5];
    const float* pb1   = (const float*)d_in[6];
    const float* pg    = (const float*)d_in[7];
    const float* pbeta = (const float*)d_in[8];
    const float* pmean = (const float*)d_in[9];
    const float* pvar  = (const float*)d_in[10];
    const float* pW2   = (const float*)d_in[11];
    const float* pb2   = (const float*)d_in[12];
    const float* aW1   = (const float*)d_in[13];
    const float* ab1   = (const float*)d_in[14];
    const float* ag    = (const float*)d_in[15];
    const float* abeta = (const float*)d_in[16];
    const float* amean = (const float*)d_in[17];
    const float* avar  = (const float*)d_in[18];
    const float* aW2   = (const float*)d_in[19];
    const float* ab2   = (const float*)d_in[20];
    const float* Wout  = (const float*)d_in[21];
    float* out = (float*)d_out;

    cudaFuncSetAttribute((const void*)knn_kernel,
                         cudaFuncAttributeMaxDynamicSharedMemorySize, KNN_SMEM);
    cudaFuncSetAttribute((const void*)qkv_kernel,
                         cudaFuncAttributeMaxDynamicSharedMemorySize, QKV_SMEM);
    cudaFuncSetAttribute((const void*)main_kernel,
                         cudaFuncAttributeMaxDynamicSharedMemorySize, MAIN_SMEM);

    fold_kernel<<<1, 512>>>(pW1, pb1, pg, pbeta, pmean, pvar,
                            aW1, ab1, ag, abeta, amean, avar,
                            pW2, aW2, Wq, Wk, Wv);
    knn_kernel<<<(BB*NN)/64, 256, KNN_SMEM>>>(xyz);
    qkv_kernel<<<(BB*NN)/64, 256, QKV_SMEM>>>(feat);
    main_kernel<<<(BB*NN)/8, 512, MAIN_SMEM>>>(xyz, pb2, ab2, Wout, out);
}